// round 14
// baseline (speedup 1.0000x reference)
#include <cuda_runtime.h>
#include <cuda.h>
#include <cuda_fp16.h>
#include <math.h>

#define HIDDEN 1152
#define HEADS  16
#define HD     72
#define BATCH  16
#define SEQ    1024
#define M_TOT  (BATCH*SEQ)
#define N_QKV  (3*HIDDEN)
#define QSCALE 0.11785113f
#define RMS_EPS 1.1920928955078125e-07f

// ---------------- scratch ----------------
__device__ __align__(256) __half g_qh[(size_t)BATCH*HEADS*SEQ*HD];
__device__ __align__(256) __half g_kh[(size_t)BATCH*HEADS*SEQ*HD];
__device__ __align__(256) __half g_vh[(size_t)BATCH*HEADS*SEQ*HD];
__device__ __align__(256) __half g_ah[(size_t)M_TOT*HIDDEN];
__device__ __align__(256) __half g_xh[(size_t)M_TOT*HIDDEN];
__device__ __align__(256) __half g_wqh[(size_t)N_QKV*HIDDEN];
__device__ __align__(256) __half g_wph[(size_t)HIDDEN*HIDDEN];

// ---------------- helpers ----------------
__device__ __forceinline__ unsigned h2u(__half2 h) {
    unsigned u;
    asm("mov.b32 %0, %1;" : "=r"(u) : "r"(*(unsigned*)&h));
    return u;
}
__device__ __forceinline__ unsigned sptr(const void* p) {
    return (unsigned)__cvta_generic_to_shared(p);
}
__device__ __forceinline__ void ldsm4(unsigned r[4], const void* p) {
    asm volatile("ldmatrix.sync.aligned.m8n8.x4.shared.b16 {%0,%1,%2,%3},[%4];"
                 : "=r"(r[0]), "=r"(r[1]), "=r"(r[2]), "=r"(r[3]) : "r"(sptr(p)));
}
__device__ __forceinline__ void ldsm2(unsigned r[2], const void* p) {
    asm volatile("ldmatrix.sync.aligned.m8n8.x2.shared.b16 {%0,%1},[%2];"
                 : "=r"(r[0]), "=r"(r[1]) : "r"(sptr(p)));
}
__device__ __forceinline__ void ldsm4t(unsigned r[4], const void* p) {
    asm volatile("ldmatrix.sync.aligned.m8n8.x4.trans.shared.b16 {%0,%1,%2,%3},[%4];"
                 : "=r"(r[0]), "=r"(r[1]), "=r"(r[2]), "=r"(r[3]) : "r"(sptr(p)));
}
__device__ __forceinline__ void ldsm2t(unsigned r[2], const void* p) {
    asm volatile("ldmatrix.sync.aligned.m8n8.x2.trans.shared.b16 {%0,%1},[%2];"
                 : "=r"(r[0]), "=r"(r[1]) : "r"(sptr(p)));
}
__device__ __forceinline__ void mma16816(float c[4], const unsigned a[4],
                                         unsigned b0, unsigned b1) {
    asm volatile(
        "mma.sync.aligned.m16n8k16.row.col.f32.f16.f16.f32 "
        "{%0,%1,%2,%3},{%4,%5,%6,%7},{%8,%9},{%0,%1,%2,%3};"
        : "+f"(c[0]), "+f"(c[1]), "+f"(c[2]), "+f"(c[3])
        : "r"(a[0]), "r"(a[1]), "r"(a[2]), "r"(a[3]), "r"(b0), "r"(b1));
}
__device__ __forceinline__ void mma16808(float c[4], unsigned a0, unsigned a1, unsigned b0) {
    asm volatile(
        "mma.sync.aligned.m16n8k8.row.col.f32.f16.f16.f32 "
        "{%0,%1,%2,%3},{%4,%5},{%6},{%0,%1,%2,%3};"
        : "+f"(c[0]), "+f"(c[1]), "+f"(c[2]), "+f"(c[3])
        : "r"(a0), "r"(a1), "r"(b0));
}

__device__ __forceinline__ void mbar_init(unsigned mbar, unsigned count) {
    asm volatile("mbarrier.init.shared.b64 [%0], %1;" :: "r"(mbar), "r"(count) : "memory");
}
__device__ __forceinline__ void mbar_expect_tx(unsigned mbar, unsigned bytes) {
    asm volatile("mbarrier.arrive.expect_tx.shared::cta.b64 _, [%0], %1;"
                 :: "r"(mbar), "r"(bytes) : "memory");
}
__device__ __forceinline__ void mbar_arrive(unsigned mbar) {
    asm volatile("mbarrier.arrive.shared::cta.b64 _, [%0];" :: "r"(mbar) : "memory");
}
__device__ __forceinline__ void mbar_wait(unsigned mbar, unsigned parity) {
    asm volatile(
        "{\n\t.reg .pred P;\n\t"
        "LW%=: mbarrier.try_wait.parity.acquire.cta.shared::cta.b64 P, [%0], %1, 0x989680;\n\t"
        "@P bra LD%=;\n\t"
        "bra LW%=;\n\t"
        "LD%=:\n\t}"
        :: "r"(mbar), "r"(parity) : "memory");
}
__device__ __forceinline__ void tma2d(unsigned smem, const CUtensorMap* m,
                                      int cx, int cy, unsigned mbar) {
    asm volatile(
        "cp.async.bulk.tensor.2d.shared::cta.global.tile.mbarrier::complete_tx::bytes "
        "[%0], [%1, {%2, %3}], [%4];"
        :: "r"(smem), "l"(m), "r"(cx), "r"(cy), "r"(mbar) : "memory");
}

// ---------------- merged fp32 -> fp16 conversion (one launch) ----------------
#define N8X (M_TOT*HIDDEN/8)
#define N8Q (N_QKV*HIDDEN/8)
#define N8P (HIDDEN*HIDDEN/8)
__global__ __launch_bounds__(256) void conv_all_kernel(const float4* __restrict__ x,
                                                       const float4* __restrict__ wq,
                                                       const float4* __restrict__ wp,
                                                       uint4* __restrict__ xh,
                                                       uint4* __restrict__ wqh,
                                                       uint4* __restrict__ wph) {
    int i = blockIdx.x * 256 + threadIdx.x;
    const float4* src;
    uint4* dst;
    int j;
    if (i < N8X)            { src = x;  dst = xh;  j = i; }
    else if (i < N8X + N8Q) { src = wq; dst = wqh; j = i - N8X; }
    else if (i < N8X + N8Q + N8P) { src = wp; dst = wph; j = i - N8X - N8Q; }
    else return;
    float4 f0 = src[2*j], f1 = src[2*j+1];
    uint4 o;
    o.x = h2u(__floats2half2_rn(f0.x, f0.y));
    o.y = h2u(__floats2half2_rn(f0.z, f0.w));
    o.z = h2u(__floats2half2_rn(f1.x, f1.y));
    o.w = h2u(__floats2half2_rn(f1.z, f1.w));
    dst[j] = o;
}

// =======================================================================
// PERSISTENT fp16 GEMM: grid = #SMs, each CTA loops tiles (stride grid).
// BM=256 BN=128 BK=64, 288 thr = 8 compute + 1 producer warp, 4-slot ring.
// Producer's chunk counter runs continuously across tiles -> ring never
// drains at tile boundaries; epilogue overlaps next tile's TMA.
// =======================================================================
#define GA_ST 16384
#define GB_ST 8192
#define STAGE_BYTES ((GA_ST+GB_ST)*2)
#define NSLOT 4
#define GEMM_SMEM (NSLOT*STAGE_BYTES + 128)
#define NCH 18    // HIDDEN/64

__global__ __launch_bounds__(288) void gemm_f16_kernel(
        const __grid_constant__ CUtensorMap mA,
        const __grid_constant__ CUtensorMap mB,
        const float* __restrict__ bias,
        float* __restrict__ out, int mode, int ntx, int T) {
    extern __shared__ __half hsm[];
    __half* As = hsm;
    __half* Bs = hsm + NSLOT*GA_ST;
    const unsigned mb = sptr(hsm) + NSLOT*STAGE_BYTES;

    const int tid  = threadIdx.x;
    const int warp = tid >> 5;
    const int lane = tid & 31;
    const int cid  = blockIdx.x;
    const int grid = gridDim.x;

    if (tid < 4)      mbar_init(mb + tid*8, 1);
    else if (tid < 8) mbar_init(mb + tid*8, 8);
    __syncthreads();

    // ---------------- producer warp ----------------
    if (warp == 8) {
        if (lane == 0) {
            int gc = 0;
            for (int tile = cid; tile < T; tile += grid) {
                const int ty = tile / ntx;
                const int m0 = ty * 256;
                const int n0 = (tile - ty*ntx) * 128;
                for (int c = 0; c < NCH; ++c, ++gc) {
                    const int slot = gc & 3;
                    if (gc >= NSLOT) mbar_wait(mb + 32 + slot*8, ((gc >> 2) - 1) & 1);
                    mbar_expect_tx(mb + slot*8, STAGE_BYTES);
                    tma2d(sptr(As + slot*GA_ST), &mA, c*64, m0, mb + slot*8);
                    tma2d(sptr(Bs + slot*GB_ST), &mB, c*64, n0, mb + slot*8);
                }
            }
        }
        return;
    }

    // ---------------- compute warps ----------------
    const int wr = warp >> 1;
    const int wc = warp & 1;
    const int g  = lane >> 2;
    const int t  = lane & 3;

    const int a_rin  = lane & 15;
    const int a_koff = lane >> 4;
    const int b_nin  = (lane & 7) + ((lane >> 4) << 3);
    const int b_koff = (lane >> 3) & 1;

    int gc = 0;
    for (int tile = cid; tile < T; tile += grid) {
        const int ty = tile / ntx;
        const int m0 = ty * 256;
        const int n0 = (tile - ty*ntx) * 128;

        float acc[4][8][4];
#pragma unroll
        for (int mi = 0; mi < 4; ++mi)
#pragma unroll
            for (int ni = 0; ni < 8; ++ni)
#pragma unroll
                for (int r = 0; r < 4; ++r) acc[mi][ni][r] = 0.f;

        for (int s = 0; s < NCH; ++s, ++gc) {
            const int slot = gc & 3;
            mbar_wait(mb + slot*8, (gc >> 2) & 1);
            const __half* cA = As + slot * GA_ST;
            const __half* cB = Bs + slot * GB_ST;
#pragma unroll
            for (int ks = 0; ks < 4; ++ks) {
                unsigned a[4][4];
#pragma unroll
                for (int mi = 0; mi < 4; ++mi) {
                    const int row = wr*64 + mi*16 + a_rin;
                    const int pc  = (ks*2 + a_koff) ^ (row & 7);
                    ldsm4(a[mi], cA + (row*8 + pc)*8);
                }
                unsigned bf[8][2];
#pragma unroll
                for (int p = 0; p < 4; ++p) {
                    const int row = wc*64 + p*16 + b_nin;
                    const int pc  = (ks*2 + b_koff) ^ (row & 7);
                    unsigned q[4];
                    ldsm4(q, cB + (row*8 + pc)*8);
                    bf[2*p][0] = q[0]; bf[2*p][1] = q[1];
                    bf[2*p+1][0] = q[2]; bf[2*p+1][1] = q[3];
                }
                if (ks == 3 && lane == 0) mbar_arrive(mb + 32 + slot*8);
#pragma unroll
                for (int mi = 0; mi < 4; ++mi)
#pragma unroll
                    for (int ni = 0; ni < 8; ++ni)
                        mma16816(acc[mi][ni], a[mi], bf[ni][0], bf[ni][1]);
            }
        }

        // ---------------- epilogue (overlaps next tile's TMA) ----------------
        if (mode == 0) {
            const int which = n0 / HIDDEN;
            __half* dst = (which == 0) ? g_qh : (which == 1) ? g_kh : g_vh;
#pragma unroll
            for (int mi = 0; mi < 4; ++mi)
#pragma unroll
                for (int ni = 0; ni < 8; ++ni) {
                    const int col = n0 + wc*64 + ni*8 + 2*t;
                    const int rem = col - which * HIDDEN;
                    const int h   = rem / HD;
                    const int d   = rem - h * HD;
                    const float b0 = bias[col], b1 = bias[col + 1];
#pragma unroll
                    for (int half_ = 0; half_ < 2; ++half_) {
                        const int row = m0 + wr*64 + mi*16 + g + half_*8;
                        const int bi  = row >> 10, si = row & (SEQ - 1);
                        __half2 v = __floats2half2_rn(acc[mi][ni][2*half_] + b0,
                                                      acc[mi][ni][2*half_+1] + b1);
                        *(__half2*)&dst[(((size_t)(bi*HEADS + h))*SEQ + si)*HD + d] = v;
                    }
                }
        } else {
#pragma unroll
            for (int mi = 0; mi < 4; ++mi)
#pragma unroll
                for (int ni = 0; ni < 8; ++ni) {
                    const int col = n0 + wc*64 + ni*8 + 2*t;
                    const float b0 = bias[col], b1 = bias[col + 1];
#pragma unroll
                    for (int half_ = 0; half_ < 2; ++half_) {
                        const int row = m0 + wr*64 + mi*16 + g + half_*8;
                        float2 v = make_float2(acc[mi][ni][2*half_] + b0,
                                               acc[mi][ni][2*half_+1] + b1);
                        *(float2*)&out[(size_t)row * HIDDEN + col] = v;
                    }
                }
        }
    }
}

// ---------------- fused RMSNorm: blockIdx.y 0 -> q (scaled), 1 -> k ----------------
__global__ __launch_bounds__(256) void rmsnorm_h_kernel(const float* __restrict__ q_gamma,
                                                        const float* __restrict__ k_gamma) {
    __half* tp = blockIdx.y ? g_kh : g_qh;
    const float* gamma = blockIdx.y ? k_gamma : q_gamma;
    const float scale = blockIdx.y ? 1.0f : QSCALE;
    const int row  = blockIdx.x * 8 + (threadIdx.x >> 5);
    const int lane = threadIdx.x & 31;
    __half* p = tp + (size_t)row * HD;
    float v0 = __half2float(p[lane]);
    float v1 = __half2float(p[32 + lane]);
    float v2 = (lane < 8) ? __half2float(p[64 + lane]) : 0.f;
    float ss = v0*v0 + v1*v1 + v2*v2;
#pragma unroll
    for (int o = 16; o; o >>= 1) ss += __shfl_xor_sync(0xffffffffu, ss, o);
    const float rs = rsqrtf(ss * (1.0f/72.0f) + RMS_EPS) * scale;
    p[lane]      = __float2half(v0 * rs * gamma[lane]);
    p[32 + lane] = __float2half(v1 * rs * gamma[32 + lane]);
    if (lane < 8) p[64 + lane] = __float2half(v2 * rs * gamma[64 + lane]);
}

// =======================================================================
// fp16 flash attention (R13): TMA-fed, decoupled mbarrier ring.
// =======================================================================
#define AQ_HALVES (128*HD)
#define AKV_HALVES (64*HD)
#define ASLOT_HALVES (2*AKV_HALVES)
#define ATTN_DATA_B ((AQ_HALVES + 3*ASLOT_HALVES)*2)   // 73728
#define ATTN_SMEM (ATTN_DATA_B + 64)

__global__ __launch_bounds__(256, 2) void attn_f16_kernel(
        const __grid_constant__ CUtensorMap mQ,
        const __grid_constant__ CUtensorMap mK,
        const __grid_constant__ CUtensorMap mV) {
    extern __shared__ __half asm_[];
    __half* Qs = asm_;
    const unsigned mb = sptr(asm_) + ATTN_DATA_B;

    const int qt = blockIdx.x;
    const int h  = blockIdx.y;
    const int b  = blockIdx.z;
    const int tid  = threadIdx.x;
    const int warp = tid >> 5;
    const int lane = tid & 31;
    const int g    = lane >> 2;
    const int t    = lane & 3;

    const int rowbase = (b*HEADS + h) * SEQ;

    if (tid < 4)      mbar_init(mb + tid*8, 1);
    else if (tid < 7) mbar_init(mb + tid*8, 8);
    __syncthreads();

    if (tid == 0) {
        mbar_expect_tx(mb + 24, AQ_HALVES*2);
        tma2d(sptr(Qs), &mQ, 0, rowbase + qt*128, mb + 24);
#pragma unroll
        for (int c = 0; c < 2; ++c) {
            __half* Kb = asm_ + AQ_HALVES + c*ASLOT_HALVES;
            mbar_expect_tx(mb + c*8, ASLOT_HALVES*2);
            tma2d(sptr(Kb),              &mK, 0, rowbase + c*64, mb + c*8);
            tma2d(sptr(Kb + AKV_HALVES), &mV, 0, rowbase + c*64, mb + c*8);
        }
    }

    float o[9][4];
#pragma unroll
    for (int n = 0; n < 9; ++n)
#pragma unroll
        for (int r = 0; r < 4; ++r) o[n][r] = 0.f;
    float l0 = 0.f, l1 = 0.f;

    const int a_rin  = lane & 15;
    const int a_koff = lane >> 4;
    const int b_nin  = (lane & 7) + ((lane >> 4) << 3);
    const int b_koff = (lane >> 3) & 1;
    const int v_sin  = (lane & 7) + ((lane >> 3) & 1) * 8;
    const int v_doff = lane >> 4;
    const int rin16  = lane & 15;

    mbar_wait(mb + 24, 0);

    const int KT = SEQ / 64;

    for (int kt = 0; kt < KT; ++kt) {
        const int slot = kt % 3;
        if (tid == 0 && kt + 2 < KT) {
            const int c2 = kt + 2;
            const int s2 = c2 % 3;
            if (c2 >= 3) mbar_wait(mb + 32 + s2*8, ((c2/3) - 1) & 1);
            __half* Kb2 = asm_ + AQ_HALVES + s2*ASLOT_HALVES;
            mbar_expect_tx(mb + s2*8, ASLOT_HALVES*2);
            tma2d(sptr(Kb2),              &mK, 0, rowbase + c2*64, mb + s2*8);
            tma2d(sptr(Kb2 + AKV_HALVES), &mV, 0, rowbase + c2*64, mb + s2*8);
        }
        mbar_wait(mb + slot*8, (kt/3) & 1);
        const __half* Kb = asm_ + AQ_HALVES + slot*ASLOT_HALVES;
        const __half* Vb = Kb + AKV_HALVES;

        float c[8][4];
#pragma unroll
        for (int n = 0; n < 8; ++n)
#pragma unroll
            for (int r = 0; r < 4; ++r) c[n][r] = 0.f;
#pragma unroll
        for (int ks = 0; ks < 4; ++ks) {
            unsigned aq[4];
            ldsm4(aq, Qs + (warp*16 + a_rin)*HD + ks*16 + a_koff*8);
#pragma unroll
            for (int p = 0; p < 4; ++p) {
                unsigned q[4];
                ldsm4(q, Kb + (p*16 + b_nin)*HD + ks*16 + b_koff*8);
                mma16816(c[2*p],   aq, q[0], q[1]);
                mma16816(c[2*p+1], aq, q[2], q[3]);
            }
        }
        {
            unsigned aq2[2];
            ldsm2(aq2, Qs + (warp*16 + rin16)*HD + 64);
#pragma unroll
            for (int p = 0; p < 4; ++p) {
                unsigned kb2[2];
                ldsm2(kb2, Kb + (p*16 + rin16)*HD + 64);
                mma16808(c[2*p],   aq2[0], aq2[1], kb2[0]);
                mma16808(c[2*p+1], aq2[0], aq2[1], kb2[1]);
            }
        }

        float sum0 = 0.f, sum1 = 0.f;
#pragma unroll
        for (int n = 0; n < 8; ++n) {
            c[n][0] = __expf(c[n][0]);
            c[n][1] = __expf(c[n][1]);
            c[n][2] = __expf(c[n][2]);
            c[n][3] = __expf(c[n][3]);
            sum0 += c[n][0] + c[n][1];
            sum1 += c[n][2] + c[n][3];
        }
        sum0 += __shfl_xor_sync(0xffffffffu, sum0, 1);
        sum0 += __shfl_xor_sync(0xffffffffu, sum0, 2);
        sum1 += __shfl_xor_sync(0xffffffffu, sum1, 1);
        sum1 += __shfl_xor_sync(0xffffffffu, sum1, 2);
        l0 += sum0;
        l1 += sum1;

        unsigned pa[4][4];
#pragma unroll
        for (int k2 = 0; k2 < 4; ++k2) {
            pa[k2][0] = h2u(__floats2half2_rn(c[2*k2][0],   c[2*k2][1]));
            pa[k2][1] = h2u(__floats2half2_rn(c[2*k2][2],   c[2*k2][3]));
            pa[k2][2] = h2u(__floats2half2_rn(c[2*k2+1][0], c[2*k2+1][1]));
            pa[k2][3] = h2u(__floats2half2_rn(c[2*k2+1][2], c[2*k2+1][3]));
        }

#pragma unroll
        for (int k2 = 0; k2 < 4; ++k2) {
            const int srow = k2*16 + v_sin;
#pragma unroll
            for (int p2 = 0; p2 < 4; ++p2) {
                unsigned q[4];
                ldsm4t(q, Vb + srow*HD + (2*p2 + v_doff)*8);
                mma16816(o[2*p2],   pa[k2], q[0], q[1]);
                mma16816(o[2*p2+1], pa[k2], q[2], q[3]);
            }
            {
                unsigned q2[2];
                ldsm2t(q2, Vb + (k2*16 + v_sin)*HD + 64);
                mma16816(o[8], pa[k2], q2[0], q2[1]);
            }
        }
        if (lane == 0) mbar_arrive(mb + 32 + slot*8);
    }

    const float inv0 = 1.0f / l0, inv1 = 1.0f / l1;
    const int q0 = qt*128 + warp*16 + g;
    __half* base0 = g_ah + ((size_t)(b*SEQ + q0)     * HIDDEN) + h*HD;
    __half* base1 = g_ah + ((size_t)(b*SEQ + q0 + 8) * HIDDEN) + h*HD;
#pragma unroll
    for (int n = 0; n < 9; ++n) {
        const int d = n*8 + 2*t;
        *(__half2*)&base0[d] = __floats2half2_rn(o[n][0]*inv0, o[n][1]*inv0);
        *(__half2*)&base1[d] = __floats2half2_rn(o[n][2]*inv1, o[n][3]*inv1);
    }
}

// ---------------- host: tensor-map encode via driver entry point ----------------
typedef CUresult (*PFN_tmeTiled_v12)(CUtensorMap*, CUtensorMapDataType, cuuint32_t,
                                     void*, const cuuint64_t*, const cuuint64_t*,
                                     const cuuint32_t*, const cuuint32_t*,
                                     CUtensorMapInterleave, CUtensorMapSwizzle,
                                     CUtensorMapL2promotion, CUtensorMapFloatOOBfill);

static void make_map(PFN_tmeTiled_v12 enc, CUtensorMap* m, void* addr,
                     unsigned long long cols, unsigned long long rows,
                     unsigned box_rows) {
    cuuint64_t dims[2]   = {cols, rows};
    cuuint64_t stride[1] = {cols * 2};
    cuuint32_t box[2]    = {64u, box_rows};
    cuuint32_t es[2]     = {1u, 1u};
    enc(m, CU_TENSOR_MAP_DATA_TYPE_FLOAT16, 2, addr, dims, stride, box, es,
        CU_TENSOR_MAP_INTERLEAVE_NONE, CU_TENSOR_MAP_SWIZZLE_128B,
        CU_TENSOR_MAP_L2_PROMOTION_L2_128B, CU_TENSOR_MAP_FLOAT_OOB_FILL_NONE);
}

static void make_map_attn(PFN_tmeTiled_v12 enc, CUtensorMap* m, void* addr,
                          unsigned box_rows) {
    cuuint64_t dims[2]   = {HD, (cuuint64_t)BATCH*HEADS*SEQ};
    cuuint64_t stride[1] = {HD * 2};
    cuuint32_t box[2]    = {HD, box_rows};
    cuuint32_t es[2]     = {1u, 1u};
    enc(m, CU_TENSOR_MAP_DATA_TYPE_FLOAT16, 2, addr, dims, stride, box, es,
        CU_TENSOR_MAP_INTERLEAVE_NONE, CU_TENSOR_MAP_SWIZZLE_NONE,
        CU_TENSOR_MAP_L2_PROMOTION_L2_128B, CU_TENSOR_MAP_FLOAT_OOB_FILL_NONE);
}

// ---------------- launch ----------------
extern "C" void kernel_launch(void* const* d_in, const int* in_sizes, int n_in,
                              void* d_out, int out_size) {
    const float* x      = (const float*)d_in[0];
    const float* w_qkv  = (const float*)d_in[1];
    const float* b_qkv  = (const float*)d_in[2];
    const float* q_gamma= (const float*)d_in[3];
    const float* k_gamma= (const float*)d_in[4];
    const float* w_proj = (const float*)d_in[5];
    const float* b_proj = (const float*)d_in[6];
    float* out = (float*)d_out;

    cudaFuncSetAttribute(gemm_f16_kernel, cudaFuncAttributeMaxDynamicSharedMemorySize, GEMM_SMEM);
    cudaFuncSetAttribute(attn_f16_kernel, cudaFuncAttributeMaxDynamicSharedMemorySize, ATTN_SMEM);

    int nsm = 148;
    cudaDeviceGetAttribute(&nsm, cudaDevAttrMultiProcessorCount, 0);

    __half *xh, *wqh, *wph, *ah, *qh, *kh, *vh;
    cudaGetSymbolAddress((void**)&xh,  g_xh);
    cudaGetSymbolAddress((void**)&wqh, g_wqh);
    cudaGetSymbolAddress((void**)&wph, g_wph);
    cudaGetSymbolAddress((void**)&ah,  g_ah);
    cudaGetSymbolAddress((void**)&qh,  g_qh);
    cudaGetSymbolAddress((void**)&kh,  g_kh);
    cudaGetSymbolAddress((void**)&vh,  g_vh);

    void* fptr = nullptr;
    cudaDriverEntryPointQueryResult qres;
    cudaGetDriverEntryPointByVersion("cuTensorMapEncodeTiled", &fptr, 12000,
                                     cudaEnableDefault, &qres);
    PFN_tmeTiled_v12 enc = (PFN_tmeTiled_v12)fptr;

    CUtensorMap mAq, mBq, mAp, mBp, mQ, mK, mV;
    make_map(enc, &mAq, xh,  HIDDEN, M_TOT,  256);
    make_map(enc, &mBq, wqh, HIDDEN, N_QKV,  128);
    make_map(enc, &mAp, ah,  HIDDEN, M_TOT,  256);
    make_map(enc, &mBp, wph, HIDDEN, HIDDEN, 128);
    make_map_attn(enc, &mQ, qh, 128);
    make_map_attn(enc, &mK, kh, 64);
    make_map_attn(enc, &mV, vh, 64);

    {   // merged fp32 -> fp16 conversion (single launch)
        const int total = N8X + N8Q + N8P;
        conv_all_kernel<<<(total + 255)/256, 256>>>(
            (const float4*)x, (const float4*)w_qkv, (const float4*)w_proj,
            (uint4*)xh, (uint4*)wqh, (uint4*)wph);
    }
    {   // QKV projection (persistent)
        const int ntx = N_QKV/128, T = ntx * (M_TOT/256);   // 27 * 64 = 1728
        gemm_f16_kernel<<<nsm, 288, GEMM_SMEM>>>(mAq, mBq, b_qkv, nullptr, 0, ntx, T);
    }
    {   // fused RMSNorm
        dim3 grid(BATCH*HEADS*SEQ/8, 2);
        rmsnorm_h_kernel<<<grid, 256>>>(q_gamma, k_gamma);
    }
    {   // attention (TMA-fed, decoupled)
        dim3 grid(SEQ/128, HEADS, BATCH);
        attn_f16_kernel<<<grid, 256, ATTN_SMEM>>>(mQ, mK, mV);
    }
    {   // output projection (persistent)
        const int ntx = HIDDEN/128, T = ntx * (M_TOT/256);  // 9 * 64 = 576
        gemm_f16_kernel<<<nsm, 288, GEMM_SMEM>>>(mAp, mBp, b_proj, out, 1, ntx, T);
    }
}

// round 15
// speedup vs baseline: 1.0334x; 1.0334x over previous
#include <cuda_runtime.h>
#include <cuda.h>
#include <cuda_fp16.h>
#include <math.h>

#define HIDDEN 1152
#define HEADS  16
#define HD     72
#define BATCH  16
#define SEQ    1024
#define M_TOT  (BATCH*SEQ)
#define N_QKV  (3*HIDDEN)
#define QSCALE 0.11785113f
#define RMS_EPS 1.1920928955078125e-07f

// ---------------- scratch ----------------
__device__ __align__(256) __half g_qh[(size_t)BATCH*HEADS*SEQ*HD];
__device__ __align__(256) __half g_kh[(size_t)BATCH*HEADS*SEQ*HD];
__device__ __align__(256) __half g_vh[(size_t)BATCH*HEADS*SEQ*HD];
__device__ __align__(256) __half g_ah[(size_t)M_TOT*HIDDEN];
__device__ __align__(256) __half g_xh[(size_t)M_TOT*HIDDEN];
__device__ __align__(256) __half g_wqh[(size_t)N_QKV*HIDDEN];
__device__ __align__(256) __half g_wph[(size_t)HIDDEN*HIDDEN];

// ---------------- helpers ----------------
__device__ __forceinline__ unsigned h2u(__half2 h) {
    unsigned u;
    asm("mov.b32 %0, %1;" : "=r"(u) : "r"(*(unsigned*)&h));
    return u;
}
__device__ __forceinline__ unsigned sptr(const void* p) {
    return (unsigned)__cvta_generic_to_shared(p);
}
__device__ __forceinline__ void ldsm4(unsigned r[4], const void* p) {
    asm volatile("ldmatrix.sync.aligned.m8n8.x4.shared.b16 {%0,%1,%2,%3},[%4];"
                 : "=r"(r[0]), "=r"(r[1]), "=r"(r[2]), "=r"(r[3]) : "r"(sptr(p)));
}
__device__ __forceinline__ void ldsm2(unsigned r[2], const void* p) {
    asm volatile("ldmatrix.sync.aligned.m8n8.x2.shared.b16 {%0,%1},[%2];"
                 : "=r"(r[0]), "=r"(r[1]) : "r"(sptr(p)));
}
__device__ __forceinline__ void ldsm4t(unsigned r[4], const void* p) {
    asm volatile("ldmatrix.sync.aligned.m8n8.x4.trans.shared.b16 {%0,%1,%2,%3},[%4];"
                 : "=r"(r[0]), "=r"(r[1]), "=r"(r[2]), "=r"(r[3]) : "r"(sptr(p)));
}
__device__ __forceinline__ void ldsm2t(unsigned r[2], const void* p) {
    asm volatile("ldmatrix.sync.aligned.m8n8.x2.trans.shared.b16 {%0,%1},[%2];"
                 : "=r"(r[0]), "=r"(r[1]) : "r"(sptr(p)));
}
__device__ __forceinline__ void mma16816(float c[4], const unsigned a[4],
                                         unsigned b0, unsigned b1) {
    asm volatile(
        "mma.sync.aligned.m16n8k16.row.col.f32.f16.f16.f32 "
        "{%0,%1,%2,%3},{%4,%5,%6,%7},{%8,%9},{%0,%1,%2,%3};"
        : "+f"(c[0]), "+f"(c[1]), "+f"(c[2]), "+f"(c[3])
        : "r"(a[0]), "r"(a[1]), "r"(a[2]), "r"(a[3]), "r"(b0), "r"(b1));
}
__device__ __forceinline__ void mma16808(float c[4], unsigned a0, unsigned a1, unsigned b0) {
    asm volatile(
        "mma.sync.aligned.m16n8k8.row.col.f32.f16.f16.f32 "
        "{%0,%1,%2,%3},{%4,%5},{%6},{%0,%1,%2,%3};"
        : "+f"(c[0]), "+f"(c[1]), "+f"(c[2]), "+f"(c[3])
        : "r"(a0), "r"(a1), "r"(b0));
}

__device__ __forceinline__ void mbar_init(unsigned mbar, unsigned count) {
    asm volatile("mbarrier.init.shared.b64 [%0], %1;" :: "r"(mbar), "r"(count) : "memory");
}
__device__ __forceinline__ void mbar_expect_tx(unsigned mbar, unsigned bytes) {
    asm volatile("mbarrier.arrive.expect_tx.shared::cta.b64 _, [%0], %1;"
                 :: "r"(mbar), "r"(bytes) : "memory");
}
__device__ __forceinline__ void mbar_arrive(unsigned mbar) {
    asm volatile("mbarrier.arrive.shared::cta.b64 _, [%0];" :: "r"(mbar) : "memory");
}
__device__ __forceinline__ void mbar_wait(unsigned mbar, unsigned parity) {
    asm volatile(
        "{\n\t.reg .pred P;\n\t"
        "LW%=: mbarrier.try_wait.parity.acquire.cta.shared::cta.b64 P, [%0], %1, 0x989680;\n\t"
        "@P bra LD%=;\n\t"
        "bra LW%=;\n\t"
        "LD%=:\n\t}"
        :: "r"(mbar), "r"(parity) : "memory");
}
__device__ __forceinline__ void tma2d(unsigned smem, const CUtensorMap* m,
                                      int cx, int cy, unsigned mbar) {
    asm volatile(
        "cp.async.bulk.tensor.2d.shared::cta.global.tile.mbarrier::complete_tx::bytes "
        "[%0], [%1, {%2, %3}], [%4];"
        :: "r"(smem), "l"(m), "r"(cx), "r"(cy), "r"(mbar) : "memory");
}

// ---------------- merged fp32 -> fp16 conversion (one launch) ----------------
#define N8X (M_TOT*HIDDEN/8)
#define N8Q (N_QKV*HIDDEN/8)
#define N8P (HIDDEN*HIDDEN/8)
__global__ __launch_bounds__(256) void conv_all_kernel(const float4* __restrict__ x,
                                                       const float4* __restrict__ wq,
                                                       const float4* __restrict__ wp,
                                                       uint4* __restrict__ xh,
                                                       uint4* __restrict__ wqh,
                                                       uint4* __restrict__ wph) {
    int i = blockIdx.x * 256 + threadIdx.x;
    const float4* src;
    uint4* dst;
    int j;
    if (i < N8X)            { src = x;  dst = xh;  j = i; }
    else if (i < N8X + N8Q) { src = wq; dst = wqh; j = i - N8X; }
    else if (i < N8X + N8Q + N8P) { src = wp; dst = wph; j = i - N8X - N8Q; }
    else return;
    float4 f0 = src[2*j], f1 = src[2*j+1];
    uint4 o;
    o.x = h2u(__floats2half2_rn(f0.x, f0.y));
    o.y = h2u(__floats2half2_rn(f0.z, f0.w));
    o.z = h2u(__floats2half2_rn(f1.x, f1.y));
    o.w = h2u(__floats2half2_rn(f1.z, f1.w));
    dst[j] = o;
}

// =======================================================================
// fp16 GEMM (R13, non-persistent): warp-specialized, BM=256 BN=128 BK=64,
// 288 threads = 8 compute + 1 producer warp, 4-slot mbarrier ring,
// early slot release after last ldmatrix of each stage.
// =======================================================================
#define GA_ST 16384
#define GB_ST 8192
#define STAGE_BYTES ((GA_ST+GB_ST)*2)
#define NSLOT 4
#define GEMM_SMEM (NSLOT*STAGE_BYTES + 128)

__global__ __launch_bounds__(288) void gemm_f16_kernel(
        const __grid_constant__ CUtensorMap mA,
        const __grid_constant__ CUtensorMap mB,
        const float* __restrict__ bias,
        float* __restrict__ out, int mode) {
    extern __shared__ __half hsm[];
    __half* As = hsm;
    __half* Bs = hsm + NSLOT*GA_ST;
    const unsigned mb = sptr(hsm) + NSLOT*STAGE_BYTES;

    const int tid  = threadIdx.x;
    const int warp = tid >> 5;
    const int lane = tid & 31;

    const int m0 = blockIdx.y * 256;
    const int n0 = blockIdx.x * 128;
    const int NS = HIDDEN / 64;

    if (tid < 4)      mbar_init(mb + tid*8, 1);
    else if (tid < 8) mbar_init(mb + tid*8, 8);
    __syncthreads();

    if (warp == 8) {
        if (lane == 0) {
            for (int c = 0; c < NS; ++c) {
                const int slot = c & 3;
                if (c >= NSLOT) mbar_wait(mb + 32 + slot*8, ((c >> 2) - 1) & 1);
                mbar_expect_tx(mb + slot*8, STAGE_BYTES);
                tma2d(sptr(As + slot*GA_ST), &mA, c*64, m0, mb + slot*8);
                tma2d(sptr(Bs + slot*GB_ST), &mB, c*64, n0, mb + slot*8);
            }
        }
        return;
    }

    const int wr = warp >> 1;
    const int wc = warp & 1;
    const int g  = lane >> 2;
    const int t  = lane & 3;

    float acc[4][8][4];
#pragma unroll
    for (int mi = 0; mi < 4; ++mi)
#pragma unroll
        for (int ni = 0; ni < 8; ++ni)
#pragma unroll
            for (int r = 0; r < 4; ++r) acc[mi][ni][r] = 0.f;

    const int a_rin  = lane & 15;
    const int a_koff = lane >> 4;
    const int b_nin  = (lane & 7) + ((lane >> 4) << 3);
    const int b_koff = (lane >> 3) & 1;

    for (int s = 0; s < NS; ++s) {
        const int slot = s & 3;
        mbar_wait(mb + slot*8, (s >> 2) & 1);
        const __half* cA = As + slot * GA_ST;
        const __half* cB = Bs + slot * GB_ST;
#pragma unroll
        for (int ks = 0; ks < 4; ++ks) {
            unsigned a[4][4];
#pragma unroll
            for (int mi = 0; mi < 4; ++mi) {
                const int row = wr*64 + mi*16 + a_rin;
                const int pc  = (ks*2 + a_koff) ^ (row & 7);
                ldsm4(a[mi], cA + (row*8 + pc)*8);
            }
            unsigned bf[8][2];
#pragma unroll
            for (int p = 0; p < 4; ++p) {
                const int row = wc*64 + p*16 + b_nin;
                const int pc  = (ks*2 + b_koff) ^ (row & 7);
                unsigned q[4];
                ldsm4(q, cB + (row*8 + pc)*8);
                bf[2*p][0] = q[0]; bf[2*p][1] = q[1];
                bf[2*p+1][0] = q[2]; bf[2*p+1][1] = q[3];
            }
            if (ks == 3 && lane == 0) mbar_arrive(mb + 32 + slot*8);
#pragma unroll
            for (int mi = 0; mi < 4; ++mi)
#pragma unroll
                for (int ni = 0; ni < 8; ++ni)
                    mma16816(acc[mi][ni], a[mi], bf[ni][0], bf[ni][1]);
        }
    }

    if (mode == 0) {
        const int which = n0 / HIDDEN;
        __half* dst = (which == 0) ? g_qh : (which == 1) ? g_kh : g_vh;
#pragma unroll
        for (int mi = 0; mi < 4; ++mi)
#pragma unroll
            for (int ni = 0; ni < 8; ++ni) {
                const int col = n0 + wc*64 + ni*8 + 2*t;
                const int rem = col - which * HIDDEN;
                const int h   = rem / HD;
                const int d   = rem - h * HD;
                const float b0 = bias[col], b1 = bias[col + 1];
#pragma unroll
                for (int half_ = 0; half_ < 2; ++half_) {
                    const int row = m0 + wr*64 + mi*16 + g + half_*8;
                    const int bi  = row >> 10, si = row & (SEQ - 1);
                    __half2 v = __floats2half2_rn(acc[mi][ni][2*half_] + b0,
                                                  acc[mi][ni][2*half_+1] + b1);
                    *(__half2*)&dst[(((size_t)(bi*HEADS + h))*SEQ + si)*HD + d] = v;
                }
            }
    } else {
#pragma unroll
        for (int mi = 0; mi < 4; ++mi)
#pragma unroll
            for (int ni = 0; ni < 8; ++ni) {
                const int col = n0 + wc*64 + ni*8 + 2*t;
                const float b0 = bias[col], b1 = bias[col + 1];
#pragma unroll
                for (int half_ = 0; half_ < 2; ++half_) {
                    const int row = m0 + wr*64 + mi*16 + g + half_*8;
                    float2 v = make_float2(acc[mi][ni][2*half_] + b0,
                                           acc[mi][ni][2*half_+1] + b1);
                    *(float2*)&out[(size_t)row * HIDDEN + col] = v;
                }
            }
    }
}

// ---------------- fused RMSNorm: blockIdx.y 0 -> q (scaled), 1 -> k ----------------
__global__ __launch_bounds__(256) void rmsnorm_h_kernel(const float* __restrict__ q_gamma,
                                                        const float* __restrict__ k_gamma) {
    __half* tp = blockIdx.y ? g_kh : g_qh;
    const float* gamma = blockIdx.y ? k_gamma : q_gamma;
    const float scale = blockIdx.y ? 1.0f : QSCALE;
    const int row  = blockIdx.x * 8 + (threadIdx.x >> 5);
    const int lane = threadIdx.x & 31;
    __half* p = tp + (size_t)row * HD;
    float v0 = __half2float(p[lane]);
    float v1 = __half2float(p[32 + lane]);
    float v2 = (lane < 8) ? __half2float(p[64 + lane]) : 0.f;
    float ss = v0*v0 + v1*v1 + v2*v2;
#pragma unroll
    for (int o = 16; o; o >>= 1) ss += __shfl_xor_sync(0xffffffffu, ss, o);
    const float rs = rsqrtf(ss * (1.0f/72.0f) + RMS_EPS) * scale;
    p[lane]      = __float2half(v0 * rs * gamma[lane]);
    p[32 + lane] = __float2half(v1 * rs * gamma[32 + lane]);
    if (lane < 8) p[64 + lane] = __float2half(v2 * rs * gamma[64 + lane]);
}

// =======================================================================
// fp16 flash attention: TMA-fed, decoupled, 4-SLOT KV ring (depth-3
// prefetch). full[4]@0..31, qfull@32, cons[4]@40..71. Stride-72 smem.
// =======================================================================
#define AQ_HALVES (128*HD)
#define AKV_HALVES (64*HD)
#define ASLOT_HALVES (2*AKV_HALVES)
#define ANSLOT 4
#define ATTN_DATA_B ((AQ_HALVES + ANSLOT*ASLOT_HALVES)*2)   // 92160
#define ATTN_SMEM (ATTN_DATA_B + 80)

__global__ __launch_bounds__(256, 2) void attn_f16_kernel(
        const __grid_constant__ CUtensorMap mQ,
        const __grid_constant__ CUtensorMap mK,
        const __grid_constant__ CUtensorMap mV) {
    extern __shared__ __half asm_[];
    __half* Qs = asm_;
    const unsigned mb = sptr(asm_) + ATTN_DATA_B;

    const int qt = blockIdx.x;
    const int h  = blockIdx.y;
    const int b  = blockIdx.z;
    const int tid  = threadIdx.x;
    const int warp = tid >> 5;
    const int lane = tid & 31;
    const int g    = lane >> 2;
    const int t    = lane & 3;

    const int rowbase = (b*HEADS + h) * SEQ;

    if (tid < 4)       mbar_init(mb + tid*8, 1);          // full[4]
    else if (tid == 4) mbar_init(mb + 32, 1);             // qfull
    else if (tid < 9)  mbar_init(mb + 40 + (tid-5)*8, 8); // cons[4]
    __syncthreads();

    if (tid == 0) {
        mbar_expect_tx(mb + 32, AQ_HALVES*2);
        tma2d(sptr(Qs), &mQ, 0, rowbase + qt*128, mb + 32);
#pragma unroll
        for (int c = 0; c < 3; ++c) {   // depth-3 preload
            __half* Kb = asm_ + AQ_HALVES + c*ASLOT_HALVES;
            mbar_expect_tx(mb + c*8, ASLOT_HALVES*2);
            tma2d(sptr(Kb),              &mK, 0, rowbase + c*64, mb + c*8);
            tma2d(sptr(Kb + AKV_HALVES), &mV, 0, rowbase + c*64, mb + c*8);
        }
    }

    float o[9][4];
#pragma unroll
    for (int n = 0; n < 9; ++n)
#pragma unroll
        for (int r = 0; r < 4; ++r) o[n][r] = 0.f;
    float l0 = 0.f, l1 = 0.f;

    const int a_rin  = lane & 15;
    const int a_koff = lane >> 4;
    const int b_nin  = (lane & 7) + ((lane >> 4) << 3);
    const int b_koff = (lane >> 3) & 1;
    const int v_sin  = (lane & 7) + ((lane >> 3) & 1) * 8;
    const int v_doff = lane >> 4;
    const int rin16  = lane & 15;

    mbar_wait(mb + 32, 0);   // Q resident

    const int KT = SEQ / 64;

    for (int kt = 0; kt < KT; ++kt) {
        const int slot = kt & 3;
        // producer: refill slot (kt+3)%4 once its previous tile is consumed
        if (tid == 0 && kt + 3 < KT) {
            const int c2 = kt + 3;
            const int s2 = c2 & 3;
            if (c2 >= 4) mbar_wait(mb + 40 + s2*8, ((c2 >> 2) - 1) & 1);
            __half* Kb2 = asm_ + AQ_HALVES + s2*ASLOT_HALVES;
            mbar_expect_tx(mb + s2*8, ASLOT_HALVES*2);
            tma2d(sptr(Kb2),              &mK, 0, rowbase + c2*64, mb + s2*8);
            tma2d(sptr(Kb2 + AKV_HALVES), &mV, 0, rowbase + c2*64, mb + s2*8);
        }
        mbar_wait(mb + slot*8, (kt >> 2) & 1);
        const __half* Kb = asm_ + AQ_HALVES + slot*ASLOT_HALVES;
        const __half* Vb = Kb + AKV_HALVES;

        // ---- S = Q @ K^T : 4x k16 + 1x k8 over d=72 ----
        float c[8][4];
#pragma unroll
        for (int n = 0; n < 8; ++n)
#pragma unroll
            for (int r = 0; r < 4; ++r) c[n][r] = 0.f;
#pragma unroll
        for (int ks = 0; ks < 4; ++ks) {
            unsigned aq[4];
            ldsm4(aq, Qs + (warp*16 + a_rin)*HD + ks*16 + a_koff*8);
#pragma unroll
            for (int p = 0; p < 4; ++p) {
                unsigned q[4];
                ldsm4(q, Kb + (p*16 + b_nin)*HD + ks*16 + b_koff*8);
                mma16816(c[2*p],   aq, q[0], q[1]);
                mma16816(c[2*p+1], aq, q[2], q[3]);
            }
        }
        {   // k8 tail
            unsigned aq2[2];
            ldsm2(aq2, Qs + (warp*16 + rin16)*HD + 64);
#pragma unroll
            for (int p = 0; p < 4; ++p) {
                unsigned kb2[2];
                ldsm2(kb2, Kb + (p*16 + rin16)*HD + 64);
                mma16808(c[2*p],   aq2[0], aq2[1], kb2[0]);
                mma16808(c[2*p+1], aq2[0], aq2[1], kb2[1]);
            }
        }

        // ---- softmax, no max subtraction ----
        float sum0 = 0.f, sum1 = 0.f;
#pragma unroll
        for (int n = 0; n < 8; ++n) {
            c[n][0] = __expf(c[n][0]);
            c[n][1] = __expf(c[n][1]);
            c[n][2] = __expf(c[n][2]);
            c[n][3] = __expf(c[n][3]);
            sum0 += c[n][0] + c[n][1];
            sum1 += c[n][2] + c[n][3];
        }
        sum0 += __shfl_xor_sync(0xffffffffu, sum0, 1);
        sum0 += __shfl_xor_sync(0xffffffffu, sum0, 2);
        sum1 += __shfl_xor_sync(0xffffffffu, sum1, 1);
        sum1 += __shfl_xor_sync(0xffffffffu, sum1, 2);
        l0 += sum0;
        l1 += sum1;

        unsigned pa[4][4];
#pragma unroll
        for (int k2 = 0; k2 < 4; ++k2) {
            pa[k2][0] = h2u(__floats2half2_rn(c[2*k2][0],   c[2*k2][1]));
            pa[k2][1] = h2u(__floats2half2_rn(c[2*k2][2],   c[2*k2][3]));
            pa[k2][2] = h2u(__floats2half2_rn(c[2*k2+1][0], c[2*k2+1][1]));
            pa[k2][3] = h2u(__floats2half2_rn(c[2*k2+1][2], c[2*k2+1][3]));
        }

        // ---- O += P @ V ----
#pragma unroll
        for (int k2 = 0; k2 < 4; ++k2) {
            const int srow = k2*16 + v_sin;
#pragma unroll
            for (int p2 = 0; p2 < 4; ++p2) {
                unsigned q[4];
                ldsm4t(q, Vb + srow*HD + (2*p2 + v_doff)*8);
                mma16816(o[2*p2],   pa[k2], q[0], q[1]);
                mma16816(o[2*p2+1], pa[k2], q[2], q[3]);
            }
            {
                unsigned q2[2];
                ldsm2t(q2, Vb + (k2*16 + v_sin)*HD + 64);
                mma16816(o[8], pa[k2], q2[0], q2[1]);
            }
        }
        if (lane == 0) mbar_arrive(mb + 40 + slot*8);
    }

    // ---- epilogue ----
    const float inv0 = 1.0f / l0, inv1 = 1.0f / l1;
    const int q0 = qt*128 + warp*16 + g;
    __half* base0 = g_ah + ((size_t)(b*SEQ + q0)     * HIDDEN) + h*HD;
    __half* base1 = g_ah + ((size_t)(b*SEQ + q0 + 8) * HIDDEN) + h*HD;
#pragma unroll
    for (int n = 0; n < 9; ++n) {
        const int d = n*8 + 2*t;
        *(__half2*)&base0[d] = __floats2half2_rn(o[n][0]*inv0, o[n][1]*inv0);
        *(__half2*)&base1[d] = __floats2half2_rn(o[n][2]*inv1, o[n][3]*inv1);
    }
}

// ---------------- host: tensor-map encode via driver entry point ----------------
typedef CUresult (*PFN_tmeTiled_v12)(CUtensorMap*, CUtensorMapDataType, cuuint32_t,
                                     void*, const cuuint64_t*, const cuuint64_t*,
                                     const cuuint32_t*, const cuuint32_t*,
                                     CUtensorMapInterleave, CUtensorMapSwizzle,
                                     CUtensorMapL2promotion, CUtensorMapFloatOOBfill);

static void make_map(PFN_tmeTiled_v12 enc, CUtensorMap* m, void* addr,
                     unsigned long long cols, unsigned long long rows,
                     unsigned box_rows) {
    cuuint64_t dims[2]   = {cols, rows};
    cuuint64_t stride[1] = {cols * 2};
    cuuint32_t box[2]    = {64u, box_rows};
    cuuint32_t es[2]     = {1u, 1u};
    enc(m, CU_TENSOR_MAP_DATA_TYPE_FLOAT16, 2, addr, dims, stride, box, es,
        CU_TENSOR_MAP_INTERLEAVE_NONE, CU_TENSOR_MAP_SWIZZLE_128B,
        CU_TENSOR_MAP_L2_PROMOTION_L2_128B, CU_TENSOR_MAP_FLOAT_OOB_FILL_NONE);
}

static void make_map_attn(PFN_tmeTiled_v12 enc, CUtensorMap* m, void* addr,
                          unsigned box_rows) {
    cuuint64_t dims[2]   = {HD, (cuuint64_t)BATCH*HEADS*SEQ};
    cuuint64_t stride[1] = {HD * 2};
    cuuint32_t box[2]    = {HD, box_rows};
    cuuint32_t es[2]     = {1u, 1u};
    enc(m, CU_TENSOR_MAP_DATA_TYPE_FLOAT16, 2, addr, dims, stride, box, es,
        CU_TENSOR_MAP_INTERLEAVE_NONE, CU_TENSOR_MAP_SWIZZLE_NONE,
        CU_TENSOR_MAP_L2_PROMOTION_L2_128B, CU_TENSOR_MAP_FLOAT_OOB_FILL_NONE);
}

// ---------------- launch ----------------
extern "C" void kernel_launch(void* const* d_in, const int* in_sizes, int n_in,
                              void* d_out, int out_size) {
    const float* x      = (const float*)d_in[0];
    const float* w_qkv  = (const float*)d_in[1];
    const float* b_qkv  = (const float*)d_in[2];
    const float* q_gamma= (const float*)d_in[3];
    const float* k_gamma= (const float*)d_in[4];
    const float* w_proj = (const float*)d_in[5];
    const float* b_proj = (const float*)d_in[6];
    float* out = (float*)d_out;

    cudaFuncSetAttribute(gemm_f16_kernel, cudaFuncAttributeMaxDynamicSharedMemorySize, GEMM_SMEM);
    cudaFuncSetAttribute(attn_f16_kernel, cudaFuncAttributeMaxDynamicSharedMemorySize, ATTN_SMEM);

    __half *xh, *wqh, *wph, *ah, *qh, *kh, *vh;
    cudaGetSymbolAddress((void**)&xh,  g_xh);
    cudaGetSymbolAddress((void**)&wqh, g_wqh);
    cudaGetSymbolAddress((void**)&wph, g_wph);
    cudaGetSymbolAddress((void**)&ah,  g_ah);
    cudaGetSymbolAddress((void**)&qh,  g_qh);
    cudaGetSymbolAddress((void**)&kh,  g_kh);
    cudaGetSymbolAddress((void**)&vh,  g_vh);

    void* fptr = nullptr;
    cudaDriverEntryPointQueryResult qres;
    cudaGetDriverEntryPointByVersion("cuTensorMapEncodeTiled", &fptr, 12000,
                                     cudaEnableDefault, &qres);
    PFN_tmeTiled_v12 enc = (PFN_tmeTiled_v12)fptr;

    CUtensorMap mAq, mBq, mAp, mBp, mQ, mK, mV;
    make_map(enc, &mAq, xh,  HIDDEN, M_TOT,  256);
    make_map(enc, &mBq, wqh, HIDDEN, N_QKV,  128);
    make_map(enc, &mAp, ah,  HIDDEN, M_TOT,  256);
    make_map(enc, &mBp, wph, HIDDEN, HIDDEN, 128);
    make_map_attn(enc, &mQ, qh, 128);
    make_map_attn(enc, &mK, kh, 64);
    make_map_attn(enc, &mV, vh, 64);

    {   // merged fp32 -> fp16 conversion (single launch)
        const int total = N8X + N8Q + N8P;
        conv_all_kernel<<<(total + 255)/256, 256>>>(
            (const float4*)x, (const float4*)w_qkv, (const float4*)w_proj,
            (uint4*)xh, (uint4*)wqh, (uint4*)wph);
    }
    {   // QKV projection
        dim3 grid(N_QKV/128, M_TOT/256);   // (27, 64)
        gemm_f16_kernel<<<grid, 288, GEMM_SMEM>>>(mAq, mBq, b_qkv, nullptr, 0);
    }
    {   // fused RMSNorm
        dim3 grid(BATCH*HEADS*SEQ/8, 2);
        rmsnorm_h_kernel<<<grid, 256>>>(q_gamma, k_gamma);
    }
    {   // attention (TMA-fed, decoupled, 4-slot ring)
        dim3 grid(SEQ/128, HEADS, BATCH);
        attn_f16_kernel<<<grid, 256, ATTN_SMEM>>>(mQ, mK, mV);
    }
    {   // output projection
        dim3 grid(HIDDEN/128, M_TOT/256);  // (9, 64)
        gemm_f16_kernel<<<grid, 288, GEMM_SMEM>>>(mAp, mBp, b_proj, out, 1);
    }
}

// round 16
// speedup vs baseline: 1.0523x; 1.0183x over previous
#include <cuda_runtime.h>
#include <cuda.h>
#include <cuda_fp16.h>
#include <math.h>

#define HIDDEN 1152
#define HEADS  16
#define HD     72
#define BATCH  16
#define SEQ    1024
#define M_TOT  (BATCH*SEQ)
#define N_QKV  (3*HIDDEN)
#define QSCALE 0.11785113f
#define LOG2E  1.44269504f
#define RMS_EPS 1.1920928955078125e-07f

// ---------------- scratch ----------------
__device__ __align__(256) __half g_qh[(size_t)BATCH*HEADS*SEQ*HD];
__device__ __align__(256) __half g_kh[(size_t)BATCH*HEADS*SEQ*HD];
__device__ __align__(256) __half g_vh[(size_t)BATCH*HEADS*SEQ*HD];
__device__ __align__(256) __half g_ah[(size_t)M_TOT*HIDDEN];
__device__ __align__(256) __half g_xh[(size_t)M_TOT*HIDDEN];
__device__ __align__(256) __half g_wqh[(size_t)N_QKV*HIDDEN];
__device__ __align__(256) __half g_wph[(size_t)HIDDEN*HIDDEN];

// ---------------- helpers ----------------
__device__ __forceinline__ unsigned h2u(__half2 h) {
    unsigned u;
    asm("mov.b32 %0, %1;" : "=r"(u) : "r"(*(unsigned*)&h));
    return u;
}
__device__ __forceinline__ unsigned sptr(const void* p) {
    return (unsigned)__cvta_generic_to_shared(p);
}
__device__ __forceinline__ void ldsm4(unsigned r[4], const void* p) {
    asm volatile("ldmatrix.sync.aligned.m8n8.x4.shared.b16 {%0,%1,%2,%3},[%4];"
                 : "=r"(r[0]), "=r"(r[1]), "=r"(r[2]), "=r"(r[3]) : "r"(sptr(p)));
}
__device__ __forceinline__ void ldsm2(unsigned r[2], const void* p) {
    asm volatile("ldmatrix.sync.aligned.m8n8.x2.shared.b16 {%0,%1},[%2];"
                 : "=r"(r[0]), "=r"(r[1]) : "r"(sptr(p)));
}
__device__ __forceinline__ void ldsm4t(unsigned r[4], const void* p) {
    asm volatile("ldmatrix.sync.aligned.m8n8.x4.trans.shared.b16 {%0,%1,%2,%3},[%4];"
                 : "=r"(r[0]), "=r"(r[1]), "=r"(r[2]), "=r"(r[3]) : "r"(sptr(p)));
}
__device__ __forceinline__ void ldsm2t(unsigned r[2], const void* p) {
    asm volatile("ldmatrix.sync.aligned.m8n8.x2.trans.shared.b16 {%0,%1},[%2];"
                 : "=r"(r[0]), "=r"(r[1]) : "r"(sptr(p)));
}
__device__ __forceinline__ void mma16816(float c[4], const unsigned a[4],
                                         unsigned b0, unsigned b1) {
    asm volatile(
        "mma.sync.aligned.m16n8k16.row.col.f32.f16.f16.f32 "
        "{%0,%1,%2,%3},{%4,%5,%6,%7},{%8,%9},{%0,%1,%2,%3};"
        : "+f"(c[0]), "+f"(c[1]), "+f"(c[2]), "+f"(c[3])
        : "r"(a[0]), "r"(a[1]), "r"(a[2]), "r"(a[3]), "r"(b0), "r"(b1));
}
__device__ __forceinline__ void mma16808(float c[4], unsigned a0, unsigned a1, unsigned b0) {
    asm volatile(
        "mma.sync.aligned.m16n8k8.row.col.f32.f16.f16.f32 "
        "{%0,%1,%2,%3},{%4,%5},{%6},{%0,%1,%2,%3};"
        : "+f"(c[0]), "+f"(c[1]), "+f"(c[2]), "+f"(c[3])
        : "r"(a0), "r"(a1), "r"(b0));
}

__device__ __forceinline__ void mbar_init(unsigned mbar, unsigned count) {
    asm volatile("mbarrier.init.shared.b64 [%0], %1;" :: "r"(mbar), "r"(count) : "memory");
}
__device__ __forceinline__ void mbar_expect_tx(unsigned mbar, unsigned bytes) {
    asm volatile("mbarrier.arrive.expect_tx.shared::cta.b64 _, [%0], %1;"
                 :: "r"(mbar), "r"(bytes) : "memory");
}
__device__ __forceinline__ void mbar_arrive(unsigned mbar) {
    asm volatile("mbarrier.arrive.shared::cta.b64 _, [%0];" :: "r"(mbar) : "memory");
}
__device__ __forceinline__ void mbar_wait(unsigned mbar, unsigned parity) {
    asm volatile(
        "{\n\t.reg .pred P;\n\t"
        "LW%=: mbarrier.try_wait.parity.acquire.cta.shared::cta.b64 P, [%0], %1, 0x989680;\n\t"
        "@P bra LD%=;\n\t"
        "bra LW%=;\n\t"
        "LD%=:\n\t}"
        :: "r"(mbar), "r"(parity) : "memory");
}
__device__ __forceinline__ void tma2d(unsigned smem, const CUtensorMap* m,
                                      int cx, int cy, unsigned mbar) {
    asm volatile(
        "cp.async.bulk.tensor.2d.shared::cta.global.tile.mbarrier::complete_tx::bytes "
        "[%0], [%1, {%2, %3}], [%4];"
        :: "r"(smem), "l"(m), "r"(cx), "r"(cy), "r"(mbar) : "memory");
}

// ---------------- merged fp32 -> fp16 conversion (one launch) ----------------
#define N8X (M_TOT*HIDDEN/8)
#define N8Q (N_QKV*HIDDEN/8)
#define N8P (HIDDEN*HIDDEN/8)
__global__ __launch_bounds__(256) void conv_all_kernel(const float4* __restrict__ x,
                                                       const float4* __restrict__ wq,
                                                       const float4* __restrict__ wp,
                                                       uint4* __restrict__ xh,
                                                       uint4* __restrict__ wqh,
                                                       uint4* __restrict__ wph) {
    int i = blockIdx.x * 256 + threadIdx.x;
    const float4* src;
    uint4* dst;
    int j;
    if (i < N8X)            { src = x;  dst = xh;  j = i; }
    else if (i < N8X + N8Q) { src = wq; dst = wqh; j = i - N8X; }
    else if (i < N8X + N8Q + N8P) { src = wp; dst = wph; j = i - N8X - N8Q; }
    else return;
    float4 f0 = src[2*j], f1 = src[2*j+1];
    uint4 o;
    o.x = h2u(__floats2half2_rn(f0.x, f0.y));
    o.y = h2u(__floats2half2_rn(f0.z, f0.w));
    o.z = h2u(__floats2half2_rn(f1.x, f1.y));
    o.w = h2u(__floats2half2_rn(f1.z, f1.w));
    dst[j] = o;
}

// =======================================================================
// fp16 GEMM: warp-specialized, BM=256 BN=128 BK=64, 288 threads =
// 8 compute + 1 producer warp, 4-slot ring, register-fragment
// DOUBLE-BUFFERING: ks+1's LDSMs issue before ks's MMAs.
// =======================================================================
#define GA_ST 16384
#define GB_ST 8192
#define STAGE_BYTES ((GA_ST+GB_ST)*2)
#define NSLOT 4
#define GEMM_SMEM (NSLOT*STAGE_BYTES + 128)

__global__ __launch_bounds__(288) void gemm_f16_kernel(
        const __grid_constant__ CUtensorMap mA,
        const __grid_constant__ CUtensorMap mB,
        const float* __restrict__ bias,
        float* __restrict__ out, int mode) {
    extern __shared__ __half hsm[];
    __half* As = hsm;
    __half* Bs = hsm + NSLOT*GA_ST;
    const unsigned mb = sptr(hsm) + NSLOT*STAGE_BYTES;

    const int tid  = threadIdx.x;
    const int warp = tid >> 5;
    const int lane = tid & 31;

    const int m0 = blockIdx.y * 256;
    const int n0 = blockIdx.x * 128;
    const int NS = HIDDEN / 64;

    if (tid < 4)      mbar_init(mb + tid*8, 1);
    else if (tid < 8) mbar_init(mb + tid*8, 8);
    __syncthreads();

    if (warp == 8) {
        if (lane == 0) {
            for (int c = 0; c < NS; ++c) {
                const int slot = c & 3;
                if (c >= NSLOT) mbar_wait(mb + 32 + slot*8, ((c >> 2) - 1) & 1);
                mbar_expect_tx(mb + slot*8, STAGE_BYTES);
                tma2d(sptr(As + slot*GA_ST), &mA, c*64, m0, mb + slot*8);
                tma2d(sptr(Bs + slot*GB_ST), &mB, c*64, n0, mb + slot*8);
            }
        }
        return;
    }

    const int wr = warp >> 1;
    const int wc = warp & 1;
    const int g  = lane >> 2;
    const int t  = lane & 3;

    float acc[4][8][4];
#pragma unroll
    for (int mi = 0; mi < 4; ++mi)
#pragma unroll
        for (int ni = 0; ni < 8; ++ni)
#pragma unroll
            for (int r = 0; r < 4; ++r) acc[mi][ni][r] = 0.f;

    const int a_rin  = lane & 15;
    const int a_koff = lane >> 4;
    const int b_nin  = (lane & 7) + ((lane >> 4) << 3);
    const int b_koff = (lane >> 3) & 1;

    unsigned afr[2][4][4];
    unsigned bfr[2][8][2];

    auto load_frags = [&](const __half* cA, const __half* cB, int ks, int buf) {
#pragma unroll
        for (int mi = 0; mi < 4; ++mi) {
            const int row = wr*64 + mi*16 + a_rin;
            const int pc  = (ks*2 + a_koff) ^ (row & 7);
            ldsm4(afr[buf][mi], cA + (row*8 + pc)*8);
        }
#pragma unroll
        for (int p = 0; p < 4; ++p) {
            const int row = wc*64 + p*16 + b_nin;
            const int pc  = (ks*2 + b_koff) ^ (row & 7);
            unsigned q[4];
            ldsm4(q, cB + (row*8 + pc)*8);
            bfr[buf][2*p][0] = q[0]; bfr[buf][2*p][1] = q[1];
            bfr[buf][2*p+1][0] = q[2]; bfr[buf][2*p+1][1] = q[3];
        }
    };

    for (int s = 0; s < NS; ++s) {
        const int slot = s & 3;
        mbar_wait(mb + slot*8, (s >> 2) & 1);
        const __half* cA = As + slot * GA_ST;
        const __half* cB = Bs + slot * GB_ST;
        load_frags(cA, cB, 0, 0);
#pragma unroll
        for (int ks = 0; ks < 4; ++ks) {
            const int buf = ks & 1;
            if (ks < 3) {
                load_frags(cA, cB, ks + 1, buf ^ 1);
                // final ldsm for this slot was just issued at ks==2
                if (ks == 2 && lane == 0) mbar_arrive(mb + 32 + slot*8);
            }
#pragma unroll
            for (int mi = 0; mi < 4; ++mi)
#pragma unroll
                for (int ni = 0; ni < 8; ++ni)
                    mma16816(acc[mi][ni], afr[buf][mi], bfr[buf][ni][0], bfr[buf][ni][1]);
        }
    }

    if (mode == 0) {
        const int which = n0 / HIDDEN;
        __half* dst = (which == 0) ? g_qh : (which == 1) ? g_kh : g_vh;
#pragma unroll
        for (int mi = 0; mi < 4; ++mi)
#pragma unroll
            for (int ni = 0; ni < 8; ++ni) {
                const int col = n0 + wc*64 + ni*8 + 2*t;
                const int rem = col - which * HIDDEN;
                const int h   = rem / HD;
                const int d   = rem - h * HD;
                const float b0 = bias[col], b1 = bias[col + 1];
#pragma unroll
                for (int half_ = 0; half_ < 2; ++half_) {
                    const int row = m0 + wr*64 + mi*16 + g + half_*8;
                    const int bi  = row >> 10, si = row & (SEQ - 1);
                    __half2 v = __floats2half2_rn(acc[mi][ni][2*half_] + b0,
                                                  acc[mi][ni][2*half_+1] + b1);
                    *(__half2*)&dst[(((size_t)(bi*HEADS + h))*SEQ + si)*HD + d] = v;
                }
            }
    } else {
#pragma unroll
        for (int mi = 0; mi < 4; ++mi)
#pragma unroll
            for (int ni = 0; ni < 8; ++ni) {
                const int col = n0 + wc*64 + ni*8 + 2*t;
                const float b0 = bias[col], b1 = bias[col + 1];
#pragma unroll
                for (int half_ = 0; half_ < 2; ++half_) {
                    const int row = m0 + wr*64 + mi*16 + g + half_*8;
                    float2 v = make_float2(acc[mi][ni][2*half_] + b0,
                                           acc[mi][ni][2*half_+1] + b1);
                    *(float2*)&out[(size_t)row * HIDDEN + col] = v;
                }
            }
    }
}

// ---------------- fused RMSNorm: blockIdx.y 0 -> q (scaled), 1 -> k ----------------
__global__ __launch_bounds__(256) void rmsnorm_h_kernel(const float* __restrict__ q_gamma,
                                                        const float* __restrict__ k_gamma) {
    __half* tp = blockIdx.y ? g_kh : g_qh;
    const float* gamma = blockIdx.y ? k_gamma : q_gamma;
    const float scale = blockIdx.y ? 1.0f : (QSCALE * LOG2E);  // exp2 folding
    const int row  = blockIdx.x * 8 + (threadIdx.x >> 5);
    const int lane = threadIdx.x & 31;
    __half* p = tp + (size_t)row * HD;
    float v0 = __half2float(p[lane]);
    float v1 = __half2float(p[32 + lane]);
    float v2 = (lane < 8) ? __half2float(p[64 + lane]) : 0.f;
    float ss = v0*v0 + v1*v1 + v2*v2;
#pragma unroll
    for (int o = 16; o; o >>= 1) ss += __shfl_xor_sync(0xffffffffu, ss, o);
    const float rs = rsqrtf(ss * (1.0f/72.0f) + RMS_EPS) * scale;
    p[lane]      = __float2half(v0 * rs * gamma[lane]);
    p[32 + lane] = __float2half(v1 * rs * gamma[32 + lane]);
    if (lane < 8) p[64 + lane] = __float2half(v2 * rs * gamma[64 + lane]);
}

// =======================================================================
// fp16 flash attention: TMA-fed, decoupled, 4-slot ring, exp2 softmax
// (log2e folded into q scale). Stride-72 smem.
// =======================================================================
#define AQ_HALVES (128*HD)
#define AKV_HALVES (64*HD)
#define ASLOT_HALVES (2*AKV_HALVES)
#define ANSLOT 4
#define ATTN_DATA_B ((AQ_HALVES + ANSLOT*ASLOT_HALVES)*2)   // 92160
#define ATTN_SMEM (ATTN_DATA_B + 80)

__global__ __launch_bounds__(256, 2) void attn_f16_kernel(
        const __grid_constant__ CUtensorMap mQ,
        const __grid_constant__ CUtensorMap mK,
        const __grid_constant__ CUtensorMap mV) {
    extern __shared__ __half asm_[];
    __half* Qs = asm_;
    const unsigned mb = sptr(asm_) + ATTN_DATA_B;

    const int qt = blockIdx.x;
    const int h  = blockIdx.y;
    const int b  = blockIdx.z;
    const int tid  = threadIdx.x;
    const int warp = tid >> 5;
    const int lane = tid & 31;
    const int g    = lane >> 2;
    const int t    = lane & 3;

    const int rowbase = (b*HEADS + h) * SEQ;

    if (tid < 4)       mbar_init(mb + tid*8, 1);
    else if (tid == 4) mbar_init(mb + 32, 1);
    else if (tid < 9)  mbar_init(mb + 40 + (tid-5)*8, 8);
    __syncthreads();

    if (tid == 0) {
        mbar_expect_tx(mb + 32, AQ_HALVES*2);
        tma2d(sptr(Qs), &mQ, 0, rowbase + qt*128, mb + 32);
#pragma unroll
        for (int c = 0; c < 3; ++c) {
            __half* Kb = asm_ + AQ_HALVES + c*ASLOT_HALVES;
            mbar_expect_tx(mb + c*8, ASLOT_HALVES*2);
            tma2d(sptr(Kb),              &mK, 0, rowbase + c*64, mb + c*8);
            tma2d(sptr(Kb + AKV_HALVES), &mV, 0, rowbase + c*64, mb + c*8);
        }
    }

    float o[9][4];
#pragma unroll
    for (int n = 0; n < 9; ++n)
#pragma unroll
        for (int r = 0; r < 4; ++r) o[n][r] = 0.f;
    float l0 = 0.f, l1 = 0.f;

    const int a_rin  = lane & 15;
    const int a_koff = lane >> 4;
    const int b_nin  = (lane & 7) + ((lane >> 4) << 3);
    const int b_koff = (lane >> 3) & 1;
    const int v_sin  = (lane & 7) + ((lane >> 3) & 1) * 8;
    const int v_doff = lane >> 4;
    const int rin16  = lane & 15;

    mbar_wait(mb + 32, 0);

    const int KT = SEQ / 64;

    for (int kt = 0; kt < KT; ++kt) {
        const int slot = kt & 3;
        if (tid == 0 && kt + 3 < KT) {
            const int c2 = kt + 3;
            const int s2 = c2 & 3;
            if (c2 >= 4) mbar_wait(mb + 40 + s2*8, ((c2 >> 2) - 1) & 1);
            __half* Kb2 = asm_ + AQ_HALVES + s2*ASLOT_HALVES;
            mbar_expect_tx(mb + s2*8, ASLOT_HALVES*2);
            tma2d(sptr(Kb2),              &mK, 0, rowbase + c2*64, mb + s2*8);
            tma2d(sptr(Kb2 + AKV_HALVES), &mV, 0, rowbase + c2*64, mb + s2*8);
        }
        mbar_wait(mb + slot*8, (kt >> 2) & 1);
        const __half* Kb = asm_ + AQ_HALVES + slot*ASLOT_HALVES;
        const __half* Vb = Kb + AKV_HALVES;

        // ---- S = Q @ K^T ----
        float c[8][4];
#pragma unroll
        for (int n = 0; n < 8; ++n)
#pragma unroll
            for (int r = 0; r < 4; ++r) c[n][r] = 0.f;
#pragma unroll
        for (int ks = 0; ks < 4; ++ks) {
            unsigned aq[4];
            ldsm4(aq, Qs + (warp*16 + a_rin)*HD + ks*16 + a_koff*8);
#pragma unroll
            for (int p = 0; p < 4; ++p) {
                unsigned q[4];
                ldsm4(q, Kb + (p*16 + b_nin)*HD + ks*16 + b_koff*8);
                mma16816(c[2*p],   aq, q[0], q[1]);
                mma16816(c[2*p+1], aq, q[2], q[3]);
            }
        }
        {
            unsigned aq2[2];
            ldsm2(aq2, Qs + (warp*16 + rin16)*HD + 64);
#pragma unroll
            for (int p = 0; p < 4; ++p) {
                unsigned kb2[2];
                ldsm2(kb2, Kb + (p*16 + rin16)*HD + 64);
                mma16808(c[2*p],   aq2[0], aq2[1], kb2[0]);
                mma16808(c[2*p+1], aq2[0], aq2[1], kb2[1]);
            }
        }

        // ---- softmax: bare exp2 (log2e pre-folded into q) ----
        float sum0 = 0.f, sum1 = 0.f;
#pragma unroll
        for (int n = 0; n < 8; ++n) {
            c[n][0] = exp2f(c[n][0]);
            c[n][1] = exp2f(c[n][1]);
            c[n][2] = exp2f(c[n][2]);
            c[n][3] = exp2f(c[n][3]);
            sum0 += c[n][0] + c[n][1];
            sum1 += c[n][2] + c[n][3];
        }
        sum0 += __shfl_xor_sync(0xffffffffu, sum0, 1);
        sum0 += __shfl_xor_sync(0xffffffffu, sum0, 2);
        sum1 += __shfl_xor_sync(0xffffffffu, sum1, 1);
        sum1 += __shfl_xor_sync(0xffffffffu, sum1, 2);
        l0 += sum0;
        l1 += sum1;

        unsigned pa[4][4];
#pragma unroll
        for (int k2 = 0; k2 < 4; ++k2) {
            pa[k2][0] = h2u(__floats2half2_rn(c[2*k2][0],   c[2*k2][1]));
            pa[k2][1] = h2u(__floats2half2_rn(c[2*k2][2],   c[2*k2][3]));
            pa[k2][2] = h2u(__floats2half2_rn(c[2*k2+1][0], c[2*k2+1][1]));
            pa[k2][3] = h2u(__floats2half2_rn(c[2*k2+1][2], c[2*k2+1][3]));
        }

        // ---- O += P @ V ----
#pragma unroll
        for (int k2 = 0; k2 < 4; ++k2) {
            const int srow = k2*16 + v_sin;
#pragma unroll
            for (int p2 = 0; p2 < 4; ++p2) {
                unsigned q[4];
                ldsm4t(q, Vb + srow*HD + (2*p2 + v_doff)*8);
                mma16816(o[2*p2],   pa[k2], q[0], q[1]);
                mma16816(o[2*p2+1], pa[k2], q[2], q[3]);
            }
            {
                unsigned q2[2];
                ldsm2t(q2, Vb + (k2*16 + v_sin)*HD + 64);
                mma16816(o[8], pa[k2], q2[0], q2[1]);
            }
        }
        if (lane == 0) mbar_arrive(mb + 40 + slot*8);
    }

    // ---- epilogue ----
    const float inv0 = 1.0f / l0, inv1 = 1.0f / l1;
    const int q0 = qt*128 + warp*16 + g;
    __half* base0 = g_ah + ((size_t)(b*SEQ + q0)     * HIDDEN) + h*HD;
    __half* base1 = g_ah + ((size_t)(b*SEQ + q0 + 8) * HIDDEN) + h*HD;
#pragma unroll
    for (int n = 0; n < 9; ++n) {
        const int d = n*8 + 2*t;
        *(__half2*)&base0[d] = __floats2half2_rn(o[n][0]*inv0, o[n][1]*inv0);
        *(__half2*)&base1[d] = __floats2half2_rn(o[n][2]*inv1, o[n][3]*inv1);
    }
}

// ---------------- host: tensor-map encode via driver entry point ----------------
typedef CUresult (*PFN_tmeTiled_v12)(CUtensorMap*, CUtensorMapDataType, cuuint32_t,
                                     void*, const cuuint64_t*, const cuuint64_t*,
                                     const cuuint32_t*, const cuuint32_t*,
                                     CUtensorMapInterleave, CUtensorMapSwizzle,
                                     CUtensorMapL2promotion, CUtensorMapFloatOOBfill);

static void make_map(PFN_tmeTiled_v12 enc, CUtensorMap* m, void* addr,
                     unsigned long long cols, unsigned long long rows,
                     unsigned box_rows) {
    cuuint64_t dims[2]   = {cols, rows};
    cuuint64_t stride[1] = {cols * 2};
    cuuint32_t box[2]    = {64u, box_rows};
    cuuint32_t es[2]     = {1u, 1u};
    enc(m, CU_TENSOR_MAP_DATA_TYPE_FLOAT16, 2, addr, dims, stride, box, es,
        CU_TENSOR_MAP_INTERLEAVE_NONE, CU_TENSOR_MAP_SWIZZLE_128B,
        CU_TENSOR_MAP_L2_PROMOTION_L2_128B, CU_TENSOR_MAP_FLOAT_OOB_FILL_NONE);
}

static void make_map_attn(PFN_tmeTiled_v12 enc, CUtensorMap* m, void* addr,
                          unsigned box_rows) {
    cuuint64_t dims[2]   = {HD, (cuuint64_t)BATCH*HEADS*SEQ};
    cuuint64_t stride[1] = {HD * 2};
    cuuint32_t box[2]    = {HD, box_rows};
    cuuint32_t es[2]     = {1u, 1u};
    enc(m, CU_TENSOR_MAP_DATA_TYPE_FLOAT16, 2, addr, dims, stride, box, es,
        CU_TENSOR_MAP_INTERLEAVE_NONE, CU_TENSOR_MAP_SWIZZLE_NONE,
        CU_TENSOR_MAP_L2_PROMOTION_L2_128B, CU_TENSOR_MAP_FLOAT_OOB_FILL_NONE);
}

// ---------------- launch ----------------
extern "C" void kernel_launch(void* const* d_in, const int* in_sizes, int n_in,
                              void* d_out, int out_size) {
    const float* x      = (const float*)d_in[0];
    const float* w_qkv  = (const float*)d_in[1];
    const float* b_qkv  = (const float*)d_in[2];
    const float* q_gamma= (const float*)d_in[3];
    const float* k_gamma= (const float*)d_in[4];
    const float* w_proj = (const float*)d_in[5];
    const float* b_proj = (const float*)d_in[6];
    float* out = (float*)d_out;

    cudaFuncSetAttribute(gemm_f16_kernel, cudaFuncAttributeMaxDynamicSharedMemorySize, GEMM_SMEM);
    cudaFuncSetAttribute(attn_f16_kernel, cudaFuncAttributeMaxDynamicSharedMemorySize, ATTN_SMEM);

    __half *xh, *wqh, *wph, *ah, *qh, *kh, *vh;
    cudaGetSymbolAddress((void**)&xh,  g_xh);
    cudaGetSymbolAddress((void**)&wqh, g_wqh);
    cudaGetSymbolAddress((void**)&wph, g_wph);
    cudaGetSymbolAddress((void**)&ah,  g_ah);
    cudaGetSymbolAddress((void**)&qh,  g_qh);
    cudaGetSymbolAddress((void**)&kh,  g_kh);
    cudaGetSymbolAddress((void**)&vh,  g_vh);

    void* fptr = nullptr;
    cudaDriverEntryPointQueryResult qres;
    cudaGetDriverEntryPointByVersion("cuTensorMapEncodeTiled", &fptr, 12000,
                                     cudaEnableDefault, &qres);
    PFN_tmeTiled_v12 enc = (PFN_tmeTiled_v12)fptr;

    CUtensorMap mAq, mBq, mAp, mBp, mQ, mK, mV;
    make_map(enc, &mAq, xh,  HIDDEN, M_TOT,  256);
    make_map(enc, &mBq, wqh, HIDDEN, N_QKV,  128);
    make_map(enc, &mAp, ah,  HIDDEN, M_TOT,  256);
    make_map(enc, &mBp, wph, HIDDEN, HIDDEN, 128);
    make_map_attn(enc, &mQ, qh, 128);
    make_map_attn(enc, &mK, kh, 64);
    make_map_attn(enc, &mV, vh, 64);

    {   // merged fp32 -> fp16 conversion (single launch)
        const int total = N8X + N8Q + N8P;
        conv_all_kernel<<<(total + 255)/256, 256>>>(
            (const float4*)x, (const float4*)w_qkv, (const float4*)w_proj,
            (uint4*)xh, (uint4*)wqh, (uint4*)wph);
    }
    {   // QKV projection
        dim3 grid(N_QKV/128, M_TOT/256);   // (27, 64)
        gemm_f16_kernel<<<grid, 288, GEMM_SMEM>>>(mAq, mBq, b_qkv, nullptr, 0);
    }
    {   // fused RMSNorm (q scale includes log2e)
        dim3 grid(BATCH*HEADS*SEQ/8, 2);
        rmsnorm_h_kernel<<<grid, 256>>>(q_gamma, k_gamma);
    }
    {   // attention
        dim3 grid(SEQ/128, HEADS, BATCH);
        attn_f16_kernel<<<grid, 256, ATTN_SMEM>>>(mQ, mK, mV);
    }
    {   // output projection
        dim3 grid(HIDDEN/128, M_TOT/256);  // (9, 64)
        gemm_f16_kernel<<<grid, 288, GEMM_SMEM>>>(mAp, mBp, b_proj, out, 1);
    }
}